// round 5
// baseline (speedup 1.0000x reference)
#include <cuda_runtime.h>
#include <cuda_fp16.h>
#include <cstdint>

// Problem constants
#define N_NODES  32768
#define N_EDGES  524288
#define NODE_DIM 128
#define HIDDEN   256
#define EDGE_DIM 32
#define KDIM     288          // 2*NODE_DIM + EDGE_DIM
#define NCOLS1   512          // HIDDEN (node) + HIDDEN (coord)
#define H_OUT_ELEMS (N_NODES * NODE_DIM)   // 4194304
#define X_OUT_ELEMS (N_NODES * 3)          // 98304

#define TILE_E   64
#define THREADS  256

// ---- device scratch (allocation-free rule: __device__ globals) ----
__device__ __half g_B1t[NCOLS1 * KDIM];      // [512][288]  fused [Wn1|Wc1]^T fp16
__device__ __half g_B2t[NODE_DIM * HIDDEN];  // [128][256]  Wn2^T fp16
__device__ __half g_hhalf[N_NODES * NODE_DIM];
__device__ int    g_is64;                    // edge_index dtype flag

// ---- SMEM layout (halfs) ----
#define SA_STRIDE 296   // 288 + 8 pad
#define SH_STRIDE 520   // 512 + 8 pad
#define SB_STRIDE 40    // 32  + 8 pad
#define SA_HALFS (TILE_E * SA_STRIDE)
#define SH_HALFS (TILE_E * SH_STRIDE)
#define SB_HALFS (128 * SB_STRIDE)
#define SW_FLOATS 1120
#define SMEM_BYTES ((SA_HALFS + SH_HALFS + SB_HALFS) * 2 + SW_FLOATS * 4 + 2*TILE_E*4 + TILE_E*4)

__device__ __forceinline__ float silu_f(float v) {
    return v / (1.0f + __expf(-v));
}

__device__ __forceinline__ void mma16816(float c[4], const unsigned a[4], const unsigned b[2]) {
    asm volatile(
        "mma.sync.aligned.m16n8k16.row.col.f32.f16.f16.f32 "
        "{%0,%1,%2,%3}, {%4,%5,%6,%7}, {%8,%9}, {%0,%1,%2,%3};"
        : "+f"(c[0]), "+f"(c[1]), "+f"(c[2]), "+f"(c[3])
        : "r"(a[0]), "r"(a[1]), "r"(a[2]), "r"(a[3]), "r"(b[0]), "r"(b[1]));
}

// ---- detect edge_index dtype: int64 has zero high words (values < 2^15) ----
__global__ void detect_idx_kernel(const int* __restrict__ e32) {
    if (threadIdx.x == 0 && blockIdx.x == 0) {
        int all_zero = 1;
        for (int i = 0; i < 64; i++)
            if (e32[2 * i + 1] != 0) { all_zero = 0; break; }
        g_is64 = all_zero;
    }
}

// ---- prep: weights -> fp16 transposed globals ----
__global__ void prep_weights_kernel(const float* __restrict__ Wn1,
                                    const float* __restrict__ Wc1,
                                    const float* __restrict__ Wn2) {
    int i = blockIdx.x * blockDim.x + threadIdx.x;
    if (i < NCOLS1 * KDIM) {
        int n = i / KDIM, k = i - n * KDIM;
        float v = (n < HIDDEN) ? Wn1[k * HIDDEN + n] : Wc1[k * HIDDEN + (n - HIDDEN)];
        g_B1t[i] = __float2half(v);
    } else if (i < NCOLS1 * KDIM + NODE_DIM * HIDDEN) {
        int j = i - NCOLS1 * KDIM;
        int n = j / HIDDEN, k = j - n * HIDDEN;
        g_B2t[j] = __float2half(Wn2[k * NODE_DIM + n]);
    }
}

// ---- prep: h -> fp16 table, and initialize out = [h | x] ----
__global__ void prep_h_kernel(const float* __restrict__ h,
                              const float* __restrict__ x,
                              float* __restrict__ out) {
    int i = blockIdx.x * blockDim.x + threadIdx.x;
    if (i < H_OUT_ELEMS) {
        float v = h[i];
        out[i] = v;
        g_hhalf[i] = __float2half(v);
    } else if (i < H_OUT_ELEMS + X_OUT_ELEMS) {
        out[i] = x[i - H_OUT_ELEMS];
    }
}

// ---- main fused edge kernel ----
__global__ __launch_bounds__(THREADS, 1)
void egnn_edge_kernel(const void* __restrict__ eidx_raw,
                      const float* __restrict__ dist,
                      const float* __restrict__ x,
                      const float* __restrict__ We1, const float* __restrict__ be1,
                      const float* __restrict__ We2, const float* __restrict__ be2,
                      const float* __restrict__ bn1, const float* __restrict__ bc1,
                      const float* __restrict__ bn2, const float* __restrict__ Wc2,
                      float* __restrict__ out) {
    extern __shared__ char smem_raw[];
    __half* sA = (__half*)smem_raw;                  // [64][296]
    __half* sH = sA + SA_HALFS;                      // [64][520]
    __half* sB = sH + SH_HALFS;                      // [128][40]
    float*  sW = (float*)(sB + SB_HALFS);            // 1120
    int*    sSrc = (int*)(sW + SW_FLOATS);           // 64
    int*    sDst = sSrc + TILE_E;                    // 64
    float*  sDist = (float*)(sDst + TILE_E);         // 64

    const int tid  = threadIdx.x;
    const int lane = tid & 31;
    const int warp = tid >> 5;
    const int wm = warp >> 2;   // 0..1 : 32-row slab
    const int wn = warp & 3;    // 0..3 : 32-col slab
    const int e0 = blockIdx.x * TILE_E;

    // edge metadata + small weights (dtype-robust index load)
    const int is64 = g_is64;
    for (int i = tid; i < TILE_E; i += THREADS) {
        int s, d;
        if (is64) {
            const long long* e64 = (const long long*)eidx_raw;
            s = (int)e64[e0 + i];
            d = (int)e64[N_EDGES + e0 + i];
        } else {
            const int* e32 = (const int*)eidx_raw;
            s = e32[e0 + i];
            d = e32[N_EDGES + e0 + i];
        }
        sSrc[i]  = s & (N_NODES - 1);
        sDst[i]  = d & (N_NODES - 1);
        sDist[i] = dist[e0 + i];
    }
    for (int i = tid; i < SW_FLOATS; i += THREADS) {
        float v;
        if (i < 32)        v = We1[i];
        else if (i < 64)   v = be1[i - 32];
        else if (i < 1088) v = We2[i - 64];
        else               v = be2[i - 1088];
        sW[i] = v;
    }
    __syncthreads();

    // gather h[src] -> sA cols [0,128), h[dst] -> sA cols [128,256)
    // 16 uint4 (128 halfs) per row half; dst offset is +16 uint4 slots.
    {
        const uint4* hh = (const uint4*)g_hhalf;
        for (int idx = tid; idx < TILE_E * 16; idx += THREADS) {
            int r = idx >> 4, s = idx & 15;
            uint4 vs = hh[(size_t)sSrc[r] * 16 + s];
            *((uint4*)(sA + r * SA_STRIDE) + s) = vs;
            uint4 vd = hh[(size_t)sDst[r] * 16 + s];
            *((uint4*)(sA + r * SA_STRIDE) + 16 + s) = vd;
        }
    }

    // edge_attr: t = silu(d*We1+be1); ea = t@We2 + be2 -> sA[:,256:288] fp16
    if (tid < TILE_E) {
        int e = tid;
        float d = sDist[e];
        float t[EDGE_DIM];
        #pragma unroll
        for (int k = 0; k < EDGE_DIM; k++) {
            float v = d * sW[k] + sW[32 + k];
            t[k] = silu_f(v);
        }
        #pragma unroll 4
        for (int j = 0; j < EDGE_DIM; j++) {
            float acc = sW[1088 + j];
            #pragma unroll
            for (int k = 0; k < EDGE_DIM; k++) acc += t[k] * sW[64 + k * EDGE_DIM + j];
            sA[e * SA_STRIDE + 256 + j] = __float2half(acc);
        }
    }
    __syncthreads();

    float c[2][4][4];

    // ================= Layer 1: [64x288] @ [288x512] =================
    for (int nc = 0; nc < 4; nc++) {
        #pragma unroll
        for (int mt = 0; mt < 2; mt++)
            #pragma unroll
            for (int nt = 0; nt < 4; nt++)
                #pragma unroll
                for (int q = 0; q < 4; q++) c[mt][nt][q] = 0.0f;

        for (int kc = 0; kc < 9; kc++) {
            __syncthreads();
            const __half* Bg = g_B1t + (size_t)(nc * 128) * KDIM + kc * 32;
            for (int idx = tid; idx < 512; idx += THREADS) {
                int n = idx >> 2, s = idx & 3;
                uint4 v = *((const uint4*)(Bg + n * KDIM) + s);
                *((uint4*)(sB + n * SB_STRIDE) + s) = v;
            }
            __syncthreads();

            #pragma unroll
            for (int ks = 0; ks < 2; ks++) {
                const int kk = ks * 16;
                unsigned a[2][4];
                #pragma unroll
                for (int mt = 0; mt < 2; mt++) {
                    int row = wm * 32 + mt * 16 + (lane >> 2);
                    int col = kc * 32 + kk + ((lane & 3) << 1);
                    const __half* base = sA + row * SA_STRIDE + col;
                    a[mt][0] = *(const unsigned*)(base);
                    a[mt][1] = *(const unsigned*)(base + 8 * SA_STRIDE);
                    a[mt][2] = *(const unsigned*)(base + 8);
                    a[mt][3] = *(const unsigned*)(base + 8 * SA_STRIDE + 8);
                }
                unsigned b[4][2];
                #pragma unroll
                for (int nt = 0; nt < 4; nt++) {
                    int n  = wn * 32 + nt * 8 + (lane >> 2);
                    int kb = kk + ((lane & 3) << 1);
                    const __half* bb = sB + n * SB_STRIDE + kb;
                    b[nt][0] = *(const unsigned*)(bb);
                    b[nt][1] = *(const unsigned*)(bb + 8);
                }
                #pragma unroll
                for (int mt = 0; mt < 2; mt++)
                    #pragma unroll
                    for (int nt = 0; nt < 4; nt++)
                        mma16816(c[mt][nt], a[mt], b[nt]);
            }
        }

        // epilogue: +bias, silu, store fp16 -> sH
        #pragma unroll
        for (int mt = 0; mt < 2; mt++) {
            #pragma unroll
            for (int nt = 0; nt < 4; nt++) {
                int row = wm * 32 + mt * 16 + (lane >> 2);
                int col = nc * 128 + wn * 32 + nt * 8 + ((lane & 3) << 1);
                const float* bias = (col < HIDDEN) ? bn1 : bc1;
                int cb = (col < HIDDEN) ? col : col - HIDDEN;
                float b0 = __ldg(&bias[cb]), b1 = __ldg(&bias[cb + 1]);
                float v0 = silu_f(c[mt][nt][0] + b0);
                float v1 = silu_f(c[mt][nt][1] + b1);
                float v2 = silu_f(c[mt][nt][2] + b0);
                float v3 = silu_f(c[mt][nt][3] + b1);
                *(__half2*)(sH + row * SH_STRIDE + col)       = __floats2half2_rn(v0, v1);
                *(__half2*)(sH + (row + 8) * SH_STRIDE + col) = __floats2half2_rn(v2, v3);
            }
        }
    }

    // ================= Layer 2: [64x256] @ [256x128] =================
    #pragma unroll
    for (int mt = 0; mt < 2; mt++)
        #pragma unroll
        for (int nt = 0; nt < 4; nt++)
            #pragma unroll
            for (int q = 0; q < 4; q++) c[mt][nt][q] = 0.0f;

    for (int kc = 0; kc < 8; kc++) {
        __syncthreads();
        const __half* Bg = g_B2t + kc * 32;
        for (int idx = tid; idx < 512; idx += THREADS) {
            int n = idx >> 2, s = idx & 3;
            uint4 v = *((const uint4*)(Bg + n * HIDDEN) + s);
            *((uint4*)(sB + n * SB_STRIDE) + s) = v;
        }
        __syncthreads();

        #pragma unroll
        for (int ks = 0; ks < 2; ks++) {
            const int kk = ks * 16;
            unsigned a[2][4];
            #pragma unroll
            for (int mt = 0; mt < 2; mt++) {
                int row = wm * 32 + mt * 16 + (lane >> 2);
                int col = kc * 32 + kk + ((lane & 3) << 1);
                const __half* base = sH + row * SH_STRIDE + col;
                a[mt][0] = *(const unsigned*)(base);
                a[mt][1] = *(const unsigned*)(base + 8 * SH_STRIDE);
                a[mt][2] = *(const unsigned*)(base + 8);
                a[mt][3] = *(const unsigned*)(base + 8 * SH_STRIDE + 8);
            }
            unsigned b[4][2];
            #pragma unroll
            for (int nt = 0; nt < 4; nt++) {
                int n  = wn * 32 + nt * 8 + (lane >> 2);
                int kb = kk + ((lane & 3) << 1);
                const __half* bb = sB + n * SB_STRIDE + kb;
                b[nt][0] = *(const unsigned*)(bb);
                b[nt][1] = *(const unsigned*)(bb + 8);
            }
            #pragma unroll
            for (int mt = 0; mt < 2; mt++)
                #pragma unroll
                for (int nt = 0; nt < 4; nt++)
                    mma16816(c[mt][nt], a[mt], b[nt]);
        }
    }

    // epilogue: m = c + bn2, atomic scatter-add into out_h[dst]
    #pragma unroll
    for (int mt = 0; mt < 2; mt++) {
        #pragma unroll
        for (int nt = 0; nt < 4; nt++) {
            int row = wm * 32 + mt * 16 + (lane >> 2);
            int col = wn * 32 + nt * 8 + ((lane & 3) << 1);
            float b0 = __ldg(&bn2[col]), b1 = __ldg(&bn2[col + 1]);
            int d0 = sDst[row];
            atomicAdd(&out[(size_t)d0 * NODE_DIM + col],     c[mt][nt][0] + b0);
            atomicAdd(&out[(size_t)d0 * NODE_DIM + col + 1], c[mt][nt][1] + b1);
            int d2 = sDst[row + 8];
            atomicAdd(&out[(size_t)d2 * NODE_DIM + col],     c[mt][nt][2] + b0);
            atomicAdd(&out[(size_t)d2 * NODE_DIM + col + 1], c[mt][nt][3] + b1);
        }
    }

    // coord branch: cw = silu(pre_c) @ Wc2  (sH cols 256..511), then x update
    {
        int e = tid >> 2;          // 0..63
        int part = tid & 3;        // quarter of the 256-dim dot
        float acc = 0.0f;
        const __half* hrow = sH + e * SH_STRIDE + 256 + part * 64;
        const float* w = Wc2 + part * 64;
        #pragma unroll 8
        for (int j = 0; j < 64; j++) acc += __half2float(hrow[j]) * __ldg(&w[j]);
        acc += __shfl_xor_sync(0xffffffff, acc, 1);
        acc += __shfl_xor_sync(0xffffffff, acc, 2);
        if (part == 0) {
            int s = sSrc[e], d = sDst[e];
            float dx = x[3 * s + 0] - x[3 * d + 0];
            float dy = x[3 * s + 1] - x[3 * d + 1];
            float dz = x[3 * s + 2] - x[3 * d + 2];
            float len = fmaxf(sqrtf(dx * dx + dy * dy + dz * dz), 1e-8f);
            float wgt = acc / len;
            atomicAdd(&out[H_OUT_ELEMS + 3 * d + 0], wgt * dx);
            atomicAdd(&out[H_OUT_ELEMS + 3 * d + 1], wgt * dy);
            atomicAdd(&out[H_OUT_ELEMS + 3 * d + 2], wgt * dz);
        }
    }
}

extern "C" void kernel_launch(void* const* d_in, const int* in_sizes, int n_in,
                              void* d_out, int out_size) {
    const float* h    = (const float*)d_in[0];
    const float* x    = (const float*)d_in[1];
    const void*  eidx = d_in[2];
    const float* dist = (const float*)d_in[3];
    const float* We1  = (const float*)d_in[4];
    const float* be1  = (const float*)d_in[5];
    const float* We2  = (const float*)d_in[6];
    const float* be2  = (const float*)d_in[7];
    const float* Wn1  = (const float*)d_in[8];
    const float* bn1  = (const float*)d_in[9];
    const float* Wn2  = (const float*)d_in[10];
    const float* bn2  = (const float*)d_in[11];
    const float* Wc1  = (const float*)d_in[12];
    const float* bc1  = (const float*)d_in[13];
    const float* Wc2  = (const float*)d_in[14];
    float* out = (float*)d_out;

    detect_idx_kernel<<<1, 32>>>((const int*)eidx);
    {
        int total_w = NCOLS1 * KDIM + NODE_DIM * HIDDEN;
        prep_weights_kernel<<<(total_w + 255) / 256, 256>>>(Wn1, Wc1, Wn2);
        int total_h = H_OUT_ELEMS + X_OUT_ELEMS;
        prep_h_kernel<<<(total_h + 255) / 256, 256>>>(h, x, out);
    }

    cudaFuncSetAttribute(egnn_edge_kernel,
                         cudaFuncAttributeMaxDynamicSharedMemorySize, SMEM_BYTES);
    egnn_edge_kernel<<<N_EDGES / TILE_E, THREADS, SMEM_BYTES>>>(
        eidx, dist, x, We1, be1, We2, be2, bn1, bc1, bn2, Wc2, out);
}

// round 6
// speedup vs baseline: 2.9836x; 2.9836x over previous
#include <cuda_runtime.h>
#include <cuda_fp16.h>
#include <cstdint>

// Problem constants
#define N_NODES  32768
#define N_EDGES  524288
#define NODE_DIM 128
#define HIDDEN   256
#define EDGE_DIM 32
#define NCOLS1   512          // HIDDEN (node) + HIDDEN (coord)
#define H_OUT_ELEMS (N_NODES * NODE_DIM)
#define X_OUT_ELEMS (N_NODES * 3)

#define TILE_E   64
#define THREADS  256

// ---- device scratch (__device__ globals; no allocation) ----
__device__ __half g_Wf[NCOLS1 * EDGE_DIM];     // [512 n][32 k] fused edge weight (We2 @ W1_edge)^T
__device__ float  g_btot[NCOLS1];              // folded bias: [bn1|bc1] + be2 @ W1_edge
__device__ __half g_Bsrc[NCOLS1 * NODE_DIM];   // [512 n][128 k]  (Wn1|Wc1 rows 0:128)^T
__device__ __half g_Bdst[NCOLS1 * NODE_DIM];   // [512 n][128 k]  (rows 128:256)^T
__device__ __half g_B2t[NODE_DIM * HIDDEN];    // [128 n][256 k]  Wn2^T
__device__ __half g_hhalf[N_NODES * NODE_DIM];
__device__ __half g_P1[(size_t)N_NODES * NCOLS1];  // h @ W_src   (fp16, 33.5MB)
__device__ __half g_P2[(size_t)N_NODES * NCOLS1];  // h @ W_dst
__device__ int    g_is64;

__device__ __forceinline__ float silu_f(float v) { return v / (1.0f + __expf(-v)); }

__device__ __forceinline__ void mma16816(float c[4], const unsigned a[4], const unsigned b[2]) {
    asm volatile(
        "mma.sync.aligned.m16n8k16.row.col.f32.f16.f16.f32 "
        "{%0,%1,%2,%3}, {%4,%5,%6,%7}, {%8,%9}, {%0,%1,%2,%3};"
        : "+f"(c[0]), "+f"(c[1]), "+f"(c[2]), "+f"(c[3])
        : "r"(a[0]), "r"(a[1]), "r"(a[2]), "r"(a[3]), "r"(b[0]), "r"(b[1]));
}

// ---- detect edge_index dtype (int64 values < 2^15 -> zero high words) ----
__global__ void detect_idx_kernel(const int* __restrict__ e32) {
    if (threadIdx.x == 0 && blockIdx.x == 0) {
        int all_zero = 1;
        for (int i = 0; i < 64; i++)
            if (e32[2 * i + 1] != 0) { all_zero = 0; break; }
        g_is64 = all_zero;
    }
}

// ---- prep: transpose/convert big weights ----
__global__ void prep_weights_kernel(const float* __restrict__ Wn1,
                                    const float* __restrict__ Wc1,
                                    const float* __restrict__ Wn2) {
    int i = blockIdx.x * blockDim.x + threadIdx.x;
    if (i < NCOLS1 * NODE_DIM) {                         // g_Bsrc
        int n = i >> 7, k = i & 127;
        float v = (n < HIDDEN) ? Wn1[k * HIDDEN + n] : Wc1[k * HIDDEN + (n - HIDDEN)];
        g_Bsrc[i] = __float2half(v);
    } else if (i < 2 * NCOLS1 * NODE_DIM) {              // g_Bdst
        int j = i - NCOLS1 * NODE_DIM;
        int n = j >> 7, k = j & 127;
        float v = (n < HIDDEN) ? Wn1[(128 + k) * HIDDEN + n]
                               : Wc1[(128 + k) * HIDDEN + (n - HIDDEN)];
        g_Bdst[j] = __float2half(v);
    } else if (i < 2 * NCOLS1 * NODE_DIM + NODE_DIM * HIDDEN) {  // g_B2t
        int j = i - 2 * NCOLS1 * NODE_DIM;
        int n = j / HIDDEN, k = j - n * HIDDEN;
        g_B2t[j] = __float2half(Wn2[k * NODE_DIM + n]);
    }
}

// ---- prep: fused edge weight Wf[n][k] = sum_j We2[k][j] * W1e[j][n], folded bias ----
__global__ void prep_wf_kernel(const float* __restrict__ Wn1,
                               const float* __restrict__ Wc1,
                               const float* __restrict__ We2,
                               const float* __restrict__ be2,
                               const float* __restrict__ bn1,
                               const float* __restrict__ bc1) {
    int n = blockIdx.x * blockDim.x + threadIdx.x;
    if (n >= NCOLS1) return;
    float w1e[EDGE_DIM];
    #pragma unroll
    for (int j = 0; j < EDGE_DIM; j++)
        w1e[j] = (n < HIDDEN) ? Wn1[(256 + j) * HIDDEN + n]
                              : Wc1[(256 + j) * HIDDEN + (n - HIDDEN)];
    #pragma unroll 4
    for (int k = 0; k < EDGE_DIM; k++) {
        float acc = 0.0f;
        #pragma unroll
        for (int j = 0; j < EDGE_DIM; j++) acc += We2[k * EDGE_DIM + j] * w1e[j];
        g_Wf[n * EDGE_DIM + k] = __float2half(acc);
    }
    float b = (n < HIDDEN) ? bn1[n] : bc1[n - HIDDEN];
    #pragma unroll
    for (int j = 0; j < EDGE_DIM; j++) b += be2[j] * w1e[j];
    g_btot[n] = b;
}

// ---- prep: h -> fp16 table + out init ----
__global__ void prep_h_kernel(const float* __restrict__ h,
                              const float* __restrict__ x,
                              float* __restrict__ out) {
    int i = blockIdx.x * blockDim.x + threadIdx.x;
    if (i < H_OUT_ELEMS) {
        float v = h[i];
        out[i] = v;
        g_hhalf[i] = __float2half(v);
    } else if (i < H_OUT_ELEMS + X_OUT_ELEMS) {
        out[i] = x[i - H_OUT_ELEMS];
    }
}

// ---- prep: node-level projections P1 = h@W_src, P2 = h@W_dst ----
#define PP_SA_STRIDE 136
#define PP_SB_STRIDE 136
#define PP_SMEM_BYTES ((64 * PP_SA_STRIDE + 128 * PP_SB_STRIDE) * 2)
__global__ __launch_bounds__(THREADS)
void prep_P_kernel() {
    extern __shared__ __half ps[];
    __half* sA = ps;                       // [64][136]
    __half* sB = ps + 64 * PP_SA_STRIDE;   // [128][136]
    const int tid = threadIdx.x, lane = tid & 31, warp = tid >> 5;
    const int wm = warp >> 2, wn = warp & 3;
    const int node0 = blockIdx.x * 64;

    for (int idx = tid; idx < 64 * 16; idx += THREADS) {
        int r = idx >> 4, s = idx & 15;
        uint4 v = ((const uint4*)g_hhalf)[(size_t)(node0 + r) * 16 + s];
        *((uint4*)(sA + r * PP_SA_STRIDE) + s) = v;
    }
    __syncthreads();

    for (int t8 = 0; t8 < 8; t8++) {
        const __half* Bt = ((t8 < 4) ? g_Bsrc : g_Bdst) + (size_t)((t8 & 3) * 128) * NODE_DIM;
        for (int idx = tid; idx < 128 * 16; idx += THREADS) {
            int n = idx >> 4, s = idx & 15;
            uint4 v = *((const uint4*)(Bt + n * NODE_DIM) + s);
            *((uint4*)(sB + n * PP_SB_STRIDE) + s) = v;
        }
        __syncthreads();

        float c[2][4][4];
        #pragma unroll
        for (int mt = 0; mt < 2; mt++)
            #pragma unroll
            for (int nt = 0; nt < 4; nt++)
                #pragma unroll
                for (int q = 0; q < 4; q++) c[mt][nt][q] = 0.0f;

        #pragma unroll
        for (int ks = 0; ks < 8; ks++) {
            const int kk = ks * 16;
            unsigned a[2][4];
            #pragma unroll
            for (int mt = 0; mt < 2; mt++) {
                int row = wm * 32 + mt * 16 + (lane >> 2);
                int col = kk + ((lane & 3) << 1);
                const __half* base = sA + row * PP_SA_STRIDE + col;
                a[mt][0] = *(const unsigned*)(base);
                a[mt][1] = *(const unsigned*)(base + 8 * PP_SA_STRIDE);
                a[mt][2] = *(const unsigned*)(base + 8);
                a[mt][3] = *(const unsigned*)(base + 8 * PP_SA_STRIDE + 8);
            }
            unsigned b[4][2];
            #pragma unroll
            for (int nt = 0; nt < 4; nt++) {
                int n = wn * 32 + nt * 8 + (lane >> 2);
                int kb = kk + ((lane & 3) << 1);
                const __half* bb = sB + n * PP_SB_STRIDE + kb;
                b[nt][0] = *(const unsigned*)(bb);
                b[nt][1] = *(const unsigned*)(bb + 8);
            }
            #pragma unroll
            for (int mt = 0; mt < 2; mt++)
                #pragma unroll
                for (int nt = 0; nt < 4; nt++)
                    mma16816(c[mt][nt], a[mt], b[nt]);
        }

        __half* gP = (t8 < 4) ? g_P1 : g_P2;
        #pragma unroll
        for (int mt = 0; mt < 2; mt++) {
            #pragma unroll
            for (int nt = 0; nt < 4; nt++) {
                int row = wm * 32 + mt * 16 + (lane >> 2);
                int col = (t8 & 3) * 128 + wn * 32 + nt * 8 + ((lane & 3) << 1);
                *(__half2*)(gP + (size_t)(node0 + row) * NCOLS1 + col) =
                    __floats2half2_rn(c[mt][nt][0], c[mt][nt][1]);
                *(__half2*)(gP + (size_t)(node0 + row + 8) * NCOLS1 + col) =
                    __floats2half2_rn(c[mt][nt][2], c[mt][nt][3]);
            }
        }
        __syncthreads();
    }
}

// ---- main fused edge kernel ----
#define SH_STRIDE 520                 // 512 + 8
#define SH_HALFS  (TILE_E * SH_STRIDE)       // 33280
#define SCRATCH_HALFS 20480                  // >= max(512*40, 128*136)
#define ST_STRIDE 40
#define ST_HALFS  (TILE_E * ST_STRIDE)       // 2560
#define MAIN_SMEM_BYTES ((SH_HALFS + SCRATCH_HALFS + ST_HALFS) * 2 + 256*4 + 2*TILE_E*4)

__global__ __launch_bounds__(THREADS)
void egnn_edge_kernel(const void* __restrict__ eidx_raw,
                      const float* __restrict__ dist,
                      const float* __restrict__ x,
                      const float* __restrict__ We1, const float* __restrict__ be1,
                      const float* __restrict__ bn2, const float* __restrict__ Wc2,
                      float* __restrict__ out) {
    extern __shared__ char smem_raw[];
    __half* sH = (__half*)smem_raw;           // [64][520]
    __half* sS = sH + SH_HALFS;               // scratch: sWf [512][40] -> sB2 [128][136]
    __half* sT = sS + SCRATCH_HALFS;          // [64][40]
    float*  sWc2 = (float*)(sT + ST_HALFS);   // 256
    int*    sSrc = (int*)(sWc2 + 256);        // 64
    int*    sDst = sSrc + TILE_E;             // 64

    const int tid  = threadIdx.x;
    const int lane = tid & 31;
    const int warp = tid >> 5;
    const int wm = warp >> 2, wn = warp & 3;
    const int e0 = blockIdx.x * TILE_E;
    const int is64 = g_is64;

    // --- init: edge meta, t (edge-MLP hidden), Wf staging, Wc2 ---
    if (tid < TILE_E) {
        int s, d;
        if (is64) {
            const long long* e64 = (const long long*)eidx_raw;
            s = (int)e64[e0 + tid];
            d = (int)e64[N_EDGES + e0 + tid];
        } else {
            const int* e32 = (const int*)eidx_raw;
            s = e32[e0 + tid];
            d = e32[N_EDGES + e0 + tid];
        }
        sSrc[tid] = s & (N_NODES - 1);
        sDst[tid] = d & (N_NODES - 1);
        float dd = dist[e0 + tid];
        #pragma unroll
        for (int k = 0; k < EDGE_DIM; k++)
            sT[tid * ST_STRIDE + k] = __float2half(silu_f(dd * __ldg(&We1[k]) + __ldg(&be1[k])));
    }
    for (int idx = tid; idx < NCOLS1 * 4; idx += THREADS) {   // sWf: 512 rows x 4 uint4
        int n = idx >> 2, s = idx & 3;
        *((uint4*)(sS + n * ST_STRIDE) + s) = ((const uint4*)(g_Wf + n * EDGE_DIM))[s];
    }
    for (int i = tid; i < HIDDEN; i += THREADS) sWc2[i] = Wc2[i];
    __syncthreads();

    // --- MMA1: edge term  [64x32] @ [32x512]  -> sH (pre-act + folded bias) ---
    {
        unsigned a1[2][2][4];
        #pragma unroll
        for (int ks = 0; ks < 2; ks++)
            #pragma unroll
            for (int mt = 0; mt < 2; mt++) {
                int row = wm * 32 + mt * 16 + (lane >> 2);
                int col = ks * 16 + ((lane & 3) << 1);
                const __half* base = sT + row * ST_STRIDE + col;
                a1[ks][mt][0] = *(const unsigned*)(base);
                a1[ks][mt][1] = *(const unsigned*)(base + 8 * ST_STRIDE);
                a1[ks][mt][2] = *(const unsigned*)(base + 8);
                a1[ks][mt][3] = *(const unsigned*)(base + 8 * ST_STRIDE + 8);
            }
        for (int nc = 0; nc < 4; nc++) {
            float c[2][4][4];
            #pragma unroll
            for (int mt = 0; mt < 2; mt++)
                #pragma unroll
                for (int nt = 0; nt < 4; nt++)
                    #pragma unroll
                    for (int q = 0; q < 4; q++) c[mt][nt][q] = 0.0f;
            #pragma unroll
            for (int ks = 0; ks < 2; ks++) {
                unsigned b[4][2];
                #pragma unroll
                for (int nt = 0; nt < 4; nt++) {
                    int n  = nc * 128 + wn * 32 + nt * 8 + (lane >> 2);
                    int kb = ks * 16 + ((lane & 3) << 1);
                    const __half* bb = sS + n * ST_STRIDE + kb;
                    b[nt][0] = *(const unsigned*)(bb);
                    b[nt][1] = *(const unsigned*)(bb + 8);
                }
                #pragma unroll
                for (int mt = 0; mt < 2; mt++)
                    #pragma unroll
                    for (int nt = 0; nt < 4; nt++)
                        mma16816(c[mt][nt], a1[ks][mt], b[nt]);
            }
            #pragma unroll
            for (int mt = 0; mt < 2; mt++) {
                #pragma unroll
                for (int nt = 0; nt < 4; nt++) {
                    int row = wm * 32 + mt * 16 + (lane >> 2);
                    int col = nc * 128 + wn * 32 + nt * 8 + ((lane & 3) << 1);
                    float b0 = g_btot[col], b1 = g_btot[col + 1];
                    *(__half2*)(sH + row * SH_STRIDE + col) =
                        __floats2half2_rn(c[mt][nt][0] + b0, c[mt][nt][1] + b1);
                    *(__half2*)(sH + (row + 8) * SH_STRIDE + col) =
                        __floats2half2_rn(c[mt][nt][2] + b0, c[mt][nt][3] + b1);
                }
            }
        }
    }
    __syncthreads();

    // --- pass: sH = silu(sH + P1[src] + P2[dst]);  also stage B2 chunk kc=0 ---
    for (int idx = tid; idx < 128 * 16; idx += THREADS) {  // sB2 kc0
        int n = idx >> 4, s = idx & 15;
        *((uint4*)(sS + n * PP_SB_STRIDE) + s) = *((const uint4*)(g_B2t + n * HIDDEN) + s);
    }
    for (int idx = tid; idx < TILE_E * 64; idx += THREADS) {
        int r = idx >> 6, ss = idx & 63;
        uint4 p1 = ((const uint4*)g_P1)[(size_t)sSrc[r] * 64 + ss];
        uint4 p2 = ((const uint4*)g_P2)[(size_t)sDst[r] * 64 + ss];
        uint4 ev = *((uint4*)(sH + r * SH_STRIDE) + ss);
        const __half2* v1 = (const __half2*)&p1;
        const __half2* v2 = (const __half2*)&p2;
        const __half2* ve = (const __half2*)&ev;
        uint4 ov;
        __half2* vo = (__half2*)&ov;
        #pragma unroll
        for (int w = 0; w < 4; w++) {
            float2 f1 = __half22float2(v1[w]);
            float2 f2 = __half22float2(v2[w]);
            float2 fe = __half22float2(ve[w]);
            vo[w] = __floats2half2_rn(silu_f(f1.x + f2.x + fe.x),
                                      silu_f(f1.y + f2.y + fe.y));
        }
        *((uint4*)(sH + r * SH_STRIDE) + ss) = ov;
    }
    __syncthreads();

    // --- Layer 2: [64x256] @ [256x128], B2 staged in two 128-k chunks ---
    float c[2][4][4];
    #pragma unroll
    for (int mt = 0; mt < 2; mt++)
        #pragma unroll
        for (int nt = 0; nt < 4; nt++)
            #pragma unroll
            for (int q = 0; q < 4; q++) c[mt][nt][q] = 0.0f;

    for (int kc = 0; kc < 2; kc++) {
        if (kc == 1) {
            __syncthreads();   // mma(kc0) done reading sS
            for (int idx = tid; idx < 128 * 16; idx += THREADS) {
                int n = idx >> 4, s = idx & 15;
                *((uint4*)(sS + n * PP_SB_STRIDE) + s) =
                    *((const uint4*)(g_B2t + n * HIDDEN + 128) + s);
            }
            __syncthreads();
        }
        #pragma unroll
        for (int ks = 0; ks < 8; ks++) {
            const int kk = ks * 16;
            unsigned a[2][4];
            #pragma unroll
            for (int mt = 0; mt < 2; mt++) {
                int row = wm * 32 + mt * 16 + (lane >> 2);
                int col = kc * 128 + kk + ((lane & 3) << 1);
                const __half* base = sH + row * SH_STRIDE + col;
                a[mt][0] = *(const unsigned*)(base);
                a[mt][1] = *(const unsigned*)(base + 8 * SH_STRIDE);
                a[mt][2] = *(const unsigned*)(base + 8);
                a[mt][3] = *(const unsigned*)(base + 8 * SH_STRIDE + 8);
            }
            unsigned b[4][2];
            #pragma unroll
            for (int nt = 0; nt < 4; nt++) {
                int n  = wn * 32 + nt * 8 + (lane >> 2);
                int kb = kk + ((lane & 3) << 1);
                const __half* bb = sS + n * PP_SB_STRIDE + kb;
                b[nt][0] = *(const unsigned*)(bb);
                b[nt][1] = *(const unsigned*)(bb + 8);
            }
            #pragma unroll
            for (int mt = 0; mt < 2; mt++)
                #pragma unroll
                for (int nt = 0; nt < 4; nt++)
                    mma16816(c[mt][nt], a[mt], b[nt]);
        }
    }

    // --- epilogue: scatter-add messages ---
    #pragma unroll
    for (int mt = 0; mt < 2; mt++) {
        #pragma unroll
        for (int nt = 0; nt < 4; nt++) {
            int row = wm * 32 + mt * 16 + (lane >> 2);
            int col = wn * 32 + nt * 8 + ((lane & 3) << 1);
            float b0 = __ldg(&bn2[col]), b1 = __ldg(&bn2[col + 1]);
            int d0 = sDst[row];
            atomicAdd(&out[(size_t)d0 * NODE_DIM + col],     c[mt][nt][0] + b0);
            atomicAdd(&out[(size_t)d0 * NODE_DIM + col + 1], c[mt][nt][1] + b1);
            int d2 = sDst[row + 8];
            atomicAdd(&out[(size_t)d2 * NODE_DIM + col],     c[mt][nt][2] + b0);
            atomicAdd(&out[(size_t)d2 * NODE_DIM + col + 1], c[mt][nt][3] + b1);
        }
    }

    // --- coord branch: cw = silu_hidden(cols 256:512) @ Wc2, x update ---
    {
        int e = tid >> 2, part = tid & 3;
        float acc = 0.0f;
        const __half* hrow = sH + e * SH_STRIDE + 256 + part * 64;
        const float* w = sWc2 + part * 64;
        #pragma unroll 8
        for (int j = 0; j < 64; j++) acc += __half2float(hrow[j]) * w[j];
        acc += __shfl_xor_sync(0xffffffff, acc, 1);
        acc += __shfl_xor_sync(0xffffffff, acc, 2);
        if (part == 0) {
            int s = sSrc[e], d = sDst[e];
            float dx = x[3 * s + 0] - x[3 * d + 0];
            float dy = x[3 * s + 1] - x[3 * d + 1];
            float dz = x[3 * s + 2] - x[3 * d + 2];
            float len = fmaxf(sqrtf(dx * dx + dy * dy + dz * dz), 1e-8f);
            float wgt = acc / len;
            atomicAdd(&out[H_OUT_ELEMS + 3 * d + 0], wgt * dx);
            atomicAdd(&out[H_OUT_ELEMS + 3 * d + 1], wgt * dy);
            atomicAdd(&out[H_OUT_ELEMS + 3 * d + 2], wgt * dz);
        }
    }
}

extern "C" void kernel_launch(void* const* d_in, const int* in_sizes, int n_in,
                              void* d_out, int out_size) {
    const float* h    = (const float*)d_in[0];
    const float* x    = (const float*)d_in[1];
    const void*  eidx = d_in[2];
    const float* dist = (const float*)d_in[3];
    const float* We1  = (const float*)d_in[4];
    const float* be1  = (const float*)d_in[5];
    const float* We2  = (const float*)d_in[6];
    const float* be2  = (const float*)d_in[7];
    const float* Wn1  = (const float*)d_in[8];
    const float* bn1  = (const float*)d_in[9];
    const float* Wn2  = (const float*)d_in[10];
    const float* bn2  = (const float*)d_in[11];
    const float* Wc1  = (const float*)d_in[12];
    const float* bc1  = (const float*)d_in[13];
    const float* Wc2  = (const float*)d_in[14];
    float* out = (float*)d_out;

    detect_idx_kernel<<<1, 32>>>((const int*)eidx);

    int total_w = 2 * NCOLS1 * NODE_DIM + NODE_DIM * HIDDEN;
    prep_weights_kernel<<<(total_w + 255) / 256, 256>>>(Wn1, Wc1, Wn2);
    prep_wf_kernel<<<2, 256>>>(Wn1, Wc1, We2, be2, bn1, bc1);

    int total_h = H_OUT_ELEMS + X_OUT_ELEMS;
    prep_h_kernel<<<(total_h + 255) / 256, 256>>>(h, x, out);

    cudaFuncSetAttribute(prep_P_kernel,
                         cudaFuncAttributeMaxDynamicSharedMemorySize, PP_SMEM_BYTES);
    prep_P_kernel<<<N_NODES / 64, THREADS, PP_SMEM_BYTES>>>();

    cudaFuncSetAttribute(egnn_edge_kernel,
                         cudaFuncAttributeMaxDynamicSharedMemorySize, MAIN_SMEM_BYTES);
    egnn_edge_kernel<<<N_EDGES / TILE_E, THREADS, MAIN_SMEM_BYTES>>>(
        eidx, dist, x, We1, be1, bn2, Wc2, out);
}

// round 7
// speedup vs baseline: 3.2643x; 1.0941x over previous
#include <cuda_runtime.h>
#include <cuda_fp16.h>
#include <cstdint>

// Problem constants
#define N_NODES  32768
#define N_EDGES  524288
#define NODE_DIM 128
#define HIDDEN   256
#define EDGE_DIM 32
#define NCOLS1   512          // HIDDEN (node) + HIDDEN (coord)
#define H_OUT_ELEMS (N_NODES * NODE_DIM)
#define X_OUT_ELEMS (N_NODES * 3)

#define TILE_E   64
#define THREADS  256

// ---- device scratch (__device__ globals; no allocation) ----
__device__ __half g_Wf[NCOLS1 * EDGE_DIM];     // [512 n][32 k] fused edge weight (We2 @ W1_edge)^T
__device__ float  g_btot[NCOLS1];              // folded bias: [bn1|bc1] + be2 @ W1_edge
__device__ __half g_Bsrc[NCOLS1 * NODE_DIM];   // [512 n][128 k]  (Wn1|Wc1 rows 0:128)^T
__device__ __half g_Bdst[NCOLS1 * NODE_DIM];   // [512 n][128 k]  (rows 128:256)^T
__device__ __half g_B2t[NODE_DIM * HIDDEN];    // [128 n][256 k]  Wn2^T
__device__ __half g_hhalf[N_NODES * NODE_DIM];
__device__ __half g_P1[(size_t)N_NODES * NCOLS1];  // h @ W_src   (fp16, 33.5MB)
__device__ __half g_P2[(size_t)N_NODES * NCOLS1];  // h @ W_dst
__device__ int    g_is64;

__device__ __forceinline__ float silu_f(float v) { return v / (1.0f + __expf(-v)); }

__device__ __forceinline__ void mma16816(float c[4], const unsigned a[4], const unsigned b[2]) {
    asm volatile(
        "mma.sync.aligned.m16n8k16.row.col.f32.f16.f16.f32 "
        "{%0,%1,%2,%3}, {%4,%5,%6,%7}, {%8,%9}, {%0,%1,%2,%3};"
        : "+f"(c[0]), "+f"(c[1]), "+f"(c[2]), "+f"(c[3])
        : "r"(a[0]), "r"(a[1]), "r"(a[2]), "r"(a[3]), "r"(b[0]), "r"(b[1]));
}

// ---- detect edge_index dtype (int64 values < 2^15 -> zero high words) ----
__global__ void detect_idx_kernel(const int* __restrict__ e32) {
    if (threadIdx.x == 0 && blockIdx.x == 0) {
        int all_zero = 1;
        for (int i = 0; i < 64; i++)
            if (e32[2 * i + 1] != 0) { all_zero = 0; break; }
        g_is64 = all_zero;
    }
}

// ---- prep: transpose/convert big weights ----
__global__ void prep_weights_kernel(const float* __restrict__ Wn1,
                                    const float* __restrict__ Wc1,
                                    const float* __restrict__ Wn2) {
    int i = blockIdx.x * blockDim.x + threadIdx.x;
    if (i < NCOLS1 * NODE_DIM) {                         // g_Bsrc
        int n = i >> 7, k = i & 127;
        float v = (n < HIDDEN) ? Wn1[k * HIDDEN + n] : Wc1[k * HIDDEN + (n - HIDDEN)];
        g_Bsrc[i] = __float2half(v);
    } else if (i < 2 * NCOLS1 * NODE_DIM) {              // g_Bdst
        int j = i - NCOLS1 * NODE_DIM;
        int n = j >> 7, k = j & 127;
        float v = (n < HIDDEN) ? Wn1[(128 + k) * HIDDEN + n]
                               : Wc1[(128 + k) * HIDDEN + (n - HIDDEN)];
        g_Bdst[j] = __float2half(v);
    } else if (i < 2 * NCOLS1 * NODE_DIM + NODE_DIM * HIDDEN) {  // g_B2t
        int j = i - 2 * NCOLS1 * NODE_DIM;
        int n = j / HIDDEN, k = j - n * HIDDEN;
        g_B2t[j] = __float2half(Wn2[k * NODE_DIM + n]);
    }
}

// ---- prep: fused edge weight Wf[n][k] = sum_j We2[k][j] * W1e[j][n], folded bias ----
__global__ void prep_wf_kernel(const float* __restrict__ Wn1,
                               const float* __restrict__ Wc1,
                               const float* __restrict__ We2,
                               const float* __restrict__ be2,
                               const float* __restrict__ bn1,
                               const float* __restrict__ bc1) {
    int n = blockIdx.x * blockDim.x + threadIdx.x;
    if (n >= NCOLS1) return;
    float w1e[EDGE_DIM];
    #pragma unroll
    for (int j = 0; j < EDGE_DIM; j++)
        w1e[j] = (n < HIDDEN) ? Wn1[(256 + j) * HIDDEN + n]
                              : Wc1[(256 + j) * HIDDEN + (n - HIDDEN)];
    #pragma unroll 4
    for (int k = 0; k < EDGE_DIM; k++) {
        float acc = 0.0f;
        #pragma unroll
        for (int j = 0; j < EDGE_DIM; j++) acc += We2[k * EDGE_DIM + j] * w1e[j];
        g_Wf[n * EDGE_DIM + k] = __float2half(acc);
    }
    float b = (n < HIDDEN) ? bn1[n] : bc1[n - HIDDEN];
    #pragma unroll
    for (int j = 0; j < EDGE_DIM; j++) b += be2[j] * w1e[j];
    g_btot[n] = b;
}

// ---- prep: h -> fp16 table + out init ----
__global__ void prep_h_kernel(const float* __restrict__ h,
                              const float* __restrict__ x,
                              float* __restrict__ out) {
    int i = blockIdx.x * blockDim.x + threadIdx.x;
    if (i < H_OUT_ELEMS) {
        float v = h[i];
        out[i] = v;
        g_hhalf[i] = __float2half(v);
    } else if (i < H_OUT_ELEMS + X_OUT_ELEMS) {
        out[i] = x[i - H_OUT_ELEMS];
    }
}

// ---- prep: node-level projections P1 = h@W_src, P2 = h@W_dst ----
#define PP_SA_STRIDE 136
#define PP_SB_STRIDE 136
#define PP_SMEM_BYTES ((64 * PP_SA_STRIDE + 128 * PP_SB_STRIDE) * 2)
__global__ __launch_bounds__(THREADS)
void prep_P_kernel() {
    extern __shared__ __half ps[];
    __half* sA = ps;                       // [64][136]
    __half* sB = ps + 64 * PP_SA_STRIDE;   // [128][136]
    const int tid = threadIdx.x, lane = tid & 31, warp = tid >> 5;
    const int wm = warp >> 2, wn = warp & 3;
    const int node0 = blockIdx.x * 64;

    for (int idx = tid; idx < 64 * 16; idx += THREADS) {
        int r = idx >> 4, s = idx & 15;
        uint4 v = ((const uint4*)g_hhalf)[(size_t)(node0 + r) * 16 + s];
        *((uint4*)(sA + r * PP_SA_STRIDE) + s) = v;
    }
    __syncthreads();

    for (int t8 = 0; t8 < 8; t8++) {
        const __half* Bt = ((t8 < 4) ? g_Bsrc : g_Bdst) + (size_t)((t8 & 3) * 128) * NODE_DIM;
        for (int idx = tid; idx < 128 * 16; idx += THREADS) {
            int n = idx >> 4, s = idx & 15;
            uint4 v = *((const uint4*)(Bt + n * NODE_DIM) + s);
            *((uint4*)(sB + n * PP_SB_STRIDE) + s) = v;
        }
        __syncthreads();

        float c[2][4][4];
        #pragma unroll
        for (int mt = 0; mt < 2; mt++)
            #pragma unroll
            for (int nt = 0; nt < 4; nt++)
                #pragma unroll
                for (int q = 0; q < 4; q++) c[mt][nt][q] = 0.0f;

        #pragma unroll
        for (int ks = 0; ks < 8; ks++) {
            const int kk = ks * 16;
            unsigned a[2][4];
            #pragma unroll
            for (int mt = 0; mt < 2; mt++) {
                int row = wm * 32 + mt * 16 + (lane >> 2);
                int col = kk + ((lane & 3) << 1);
                const __half* base = sA + row * PP_SA_STRIDE + col;
                a[mt][0] = *(const unsigned*)(base);
                a[mt][1] = *(const unsigned*)(base + 8 * PP_SA_STRIDE);
                a[mt][2] = *(const unsigned*)(base + 8);
                a[mt][3] = *(const unsigned*)(base + 8 * PP_SA_STRIDE + 8);
            }
            unsigned b[4][2];
            #pragma unroll
            for (int nt = 0; nt < 4; nt++) {
                int n = wn * 32 + nt * 8 + (lane >> 2);
                int kb = kk + ((lane & 3) << 1);
                const __half* bb = sB + n * PP_SB_STRIDE + kb;
                b[nt][0] = *(const unsigned*)(bb);
                b[nt][1] = *(const unsigned*)(bb + 8);
            }
            #pragma unroll
            for (int mt = 0; mt < 2; mt++)
                #pragma unroll
                for (int nt = 0; nt < 4; nt++)
                    mma16816(c[mt][nt], a[mt], b[nt]);
        }

        __half* gP = (t8 < 4) ? g_P1 : g_P2;
        #pragma unroll
        for (int mt = 0; mt < 2; mt++) {
            #pragma unroll
            for (int nt = 0; nt < 4; nt++) {
                int row = wm * 32 + mt * 16 + (lane >> 2);
                int col = (t8 & 3) * 128 + wn * 32 + nt * 8 + ((lane & 3) << 1);
                *(__half2*)(gP + (size_t)(node0 + row) * NCOLS1 + col) =
                    __floats2half2_rn(c[mt][nt][0], c[mt][nt][1]);
                *(__half2*)(gP + (size_t)(node0 + row + 8) * NCOLS1 + col) =
                    __floats2half2_rn(c[mt][nt][2], c[mt][nt][3]);
            }
        }
        __syncthreads();
    }
}

// ---- main fused edge kernel ----
// SMEM: sH [64][520] + sT [64][40] + Wc2 + idx = ~73 KB  -> 3 CTAs/SM
#define SH_STRIDE 520
#define SH_HALFS  (TILE_E * SH_STRIDE)       // 33280
#define ST_STRIDE 40
#define ST_HALFS  (TILE_E * ST_STRIDE)       // 2560
#define MAIN_SMEM_BYTES ((SH_HALFS + ST_HALFS) * 2 + 256*4 + 2*TILE_E*4)

__global__ __launch_bounds__(THREADS, 3)
void egnn_edge_kernel(const void* __restrict__ eidx_raw,
                      const float* __restrict__ dist,
                      const float* __restrict__ x,
                      const float* __restrict__ We1, const float* __restrict__ be1,
                      const float* __restrict__ bn2, const float* __restrict__ Wc2,
                      float* __restrict__ out) {
    extern __shared__ char smem_raw[];
    __half* sH = (__half*)smem_raw;           // [64][520]
    __half* sT = sH + SH_HALFS;               // [64][40]
    float*  sWc2 = (float*)(sT + ST_HALFS);   // 256
    int*    sSrc = (int*)(sWc2 + 256);        // 64
    int*    sDst = sSrc + TILE_E;             // 64

    const int tid  = threadIdx.x;
    const int lane = tid & 31;
    const int warp = tid >> 5;
    const int wm = warp >> 2, wn = warp & 3;
    const int e0 = blockIdx.x * TILE_E;
    const int is64 = g_is64;

    // --- init: edge meta, t (edge-MLP hidden), Wc2 ---
    if (tid < TILE_E) {
        int s, d;
        if (is64) {
            const long long* e64 = (const long long*)eidx_raw;
            s = (int)e64[e0 + tid];
            d = (int)e64[N_EDGES + e0 + tid];
        } else {
            const int* e32 = (const int*)eidx_raw;
            s = e32[e0 + tid];
            d = e32[N_EDGES + e0 + tid];
        }
        sSrc[tid] = s & (N_NODES - 1);
        sDst[tid] = d & (N_NODES - 1);
        float dd = dist[e0 + tid];
        #pragma unroll
        for (int k = 0; k < EDGE_DIM; k++)
            sT[tid * ST_STRIDE + k] = __float2half(silu_f(dd * __ldg(&We1[k]) + __ldg(&be1[k])));
    }
    for (int i = tid; i < HIDDEN; i += THREADS) sWc2[i] = Wc2[i];
    __syncthreads();

    // --- MMA1: edge term  [64x32] @ [32x512] -> sH (pre-act + folded bias) ---
    // B fragments read directly from g_Wf (L1/L2-resident, same for all CTAs).
    {
        unsigned a1[2][2][4];
        #pragma unroll
        for (int ks = 0; ks < 2; ks++)
            #pragma unroll
            for (int mt = 0; mt < 2; mt++) {
                int row = wm * 32 + mt * 16 + (lane >> 2);
                int col = ks * 16 + ((lane & 3) << 1);
                const __half* base = sT + row * ST_STRIDE + col;
                a1[ks][mt][0] = *(const unsigned*)(base);
                a1[ks][mt][1] = *(const unsigned*)(base + 8 * ST_STRIDE);
                a1[ks][mt][2] = *(const unsigned*)(base + 8);
                a1[ks][mt][3] = *(const unsigned*)(base + 8 * ST_STRIDE + 8);
            }
        for (int nc = 0; nc < 4; nc++) {
            float c[2][4][4];
            #pragma unroll
            for (int mt = 0; mt < 2; mt++)
                #pragma unroll
                for (int nt = 0; nt < 4; nt++)
                    #pragma unroll
                    for (int q = 0; q < 4; q++) c[mt][nt][q] = 0.0f;
            #pragma unroll
            for (int ks = 0; ks < 2; ks++) {
                unsigned b[4][2];
                #pragma unroll
                for (int nt = 0; nt < 4; nt++) {
                    int n  = nc * 128 + wn * 32 + nt * 8 + (lane >> 2);
                    int kb = ks * 16 + ((lane & 3) << 1);
                    const __half* bb = g_Wf + n * EDGE_DIM + kb;
                    b[nt][0] = *(const unsigned*)(bb);
                    b[nt][1] = *(const unsigned*)(bb + 8);
                }
                #pragma unroll
                for (int mt = 0; mt < 2; mt++)
                    #pragma unroll
                    for (int nt = 0; nt < 4; nt++)
                        mma16816(c[mt][nt], a1[ks][mt], b[nt]);
            }
            #pragma unroll
            for (int mt = 0; mt < 2; mt++) {
                #pragma unroll
                for (int nt = 0; nt < 4; nt++) {
                    int row = wm * 32 + mt * 16 + (lane >> 2);
                    int col = nc * 128 + wn * 32 + nt * 8 + ((lane & 3) << 1);
                    float b0 = g_btot[col], b1 = g_btot[col + 1];
                    *(__half2*)(sH + row * SH_STRIDE + col) =
                        __floats2half2_rn(c[mt][nt][0] + b0, c[mt][nt][1] + b1);
                    *(__half2*)(sH + (row + 8) * SH_STRIDE + col) =
                        __floats2half2_rn(c[mt][nt][2] + b0, c[mt][nt][3] + b1);
                }
            }
        }
    }
    __syncthreads();

    // --- pass: sH = silu(sH + P1[src] + P2[dst]) ---
    for (int idx = tid; idx < TILE_E * 64; idx += THREADS) {
        int r = idx >> 6, ss = idx & 63;
        uint4 p1 = ((const uint4*)g_P1)[(size_t)sSrc[r] * 64 + ss];
        uint4 p2 = ((const uint4*)g_P2)[(size_t)sDst[r] * 64 + ss];
        uint4 ev = *((uint4*)(sH + r * SH_STRIDE) + ss);
        const __half2* v1 = (const __half2*)&p1;
        const __half2* v2 = (const __half2*)&p2;
        const __half2* ve = (const __half2*)&ev;
        uint4 ov;
        __half2* vo = (__half2*)&ov;
        #pragma unroll
        for (int w = 0; w < 4; w++) {
            float2 f1 = __half22float2(v1[w]);
            float2 f2 = __half22float2(v2[w]);
            float2 fe = __half22float2(ve[w]);
            vo[w] = __floats2half2_rn(silu_f(f1.x + f2.x + fe.x),
                                      silu_f(f1.y + f2.y + fe.y));
        }
        *((uint4*)(sH + r * SH_STRIDE) + ss) = ov;
    }
    __syncthreads();

    // --- Layer 2: [64x256] @ [256x128], B read directly from g_B2t ---
    float c[2][4][4];
    #pragma unroll
    for (int mt = 0; mt < 2; mt++)
        #pragma unroll
        for (int nt = 0; nt < 4; nt++)
            #pragma unroll
            for (int q = 0; q < 4; q++) c[mt][nt][q] = 0.0f;

    #pragma unroll
    for (int ks = 0; ks < 16; ks++) {
        const int kk = ks * 16;
        unsigned a[2][4];
        #pragma unroll
        for (int mt = 0; mt < 2; mt++) {
            int row = wm * 32 + mt * 16 + (lane >> 2);
            int col = kk + ((lane & 3) << 1);
            const __half* base = sH + row * SH_STRIDE + col;
            a[mt][0] = *(const unsigned*)(base);
            a[mt][1] = *(const unsigned*)(base + 8 * SH_STRIDE);
            a[mt][2] = *(const unsigned*)(base + 8);
            a[mt][3] = *(const unsigned*)(base + 8 * SH_STRIDE + 8);
        }
        unsigned b[4][2];
        #pragma unroll
        for (int nt = 0; nt < 4; nt++) {
            int n  = wn * 32 + nt * 8 + (lane >> 2);
            int kb = kk + ((lane & 3) << 1);
            const __half* bb = g_B2t + n * HIDDEN + kb;
            b[nt][0] = *(const unsigned*)(bb);
            b[nt][1] = *(const unsigned*)(bb + 8);
        }
        #pragma unroll
        for (int mt = 0; mt < 2; mt++)
            #pragma unroll
            for (int nt = 0; nt < 4; nt++)
                mma16816(c[mt][nt], a[mt], b[nt]);
    }

    // --- epilogue: scatter-add messages ---
    #pragma unroll
    for (int mt = 0; mt < 2; mt++) {
        #pragma unroll
        for (int nt = 0; nt < 4; nt++) {
            int row = wm * 32 + mt * 16 + (lane >> 2);
            int col = wn * 32 + nt * 8 + ((lane & 3) << 1);
            float b0 = __ldg(&bn2[col]), b1 = __ldg(&bn2[col + 1]);
            int d0 = sDst[row];
            atomicAdd(&out[(size_t)d0 * NODE_DIM + col],     c[mt][nt][0] + b0);
            atomicAdd(&out[(size_t)d0 * NODE_DIM + col + 1], c[mt][nt][1] + b1);
            int d2 = sDst[row + 8];
            atomicAdd(&out[(size_t)d2 * NODE_DIM + col],     c[mt][nt][2] + b0);
            atomicAdd(&out[(size_t)d2 * NODE_DIM + col + 1], c[mt][nt][3] + b1);
        }
    }

    // --- coord branch: cw = silu_hidden(cols 256:512) @ Wc2, x update ---
    {
        int e = tid >> 2, part = tid & 3;
        float acc = 0.0f;
        const __half* hrow = sH + e * SH_STRIDE + 256 + part * 64;
        const float* w = sWc2 + part * 64;
        #pragma unroll 8
        for (int j = 0; j < 64; j++) acc += __half2float(hrow[j]) * w[j];
        acc += __shfl_xor_sync(0xffffffff, acc, 1);
        acc += __shfl_xor_sync(0xffffffff, acc, 2);
        if (part == 0) {
            int s = sSrc[e], d = sDst[e];
            float dx = x[3 * s + 0] - x[3 * d + 0];
            float dy = x[3 * s + 1] - x[3 * d + 1];
            float dz = x[3 * s + 2] - x[3 * d + 2];
            float len = fmaxf(sqrtf(dx * dx + dy * dy + dz * dz), 1e-8f);
            float wgt = acc / len;
            atomicAdd(&out[H_OUT_ELEMS + 3 * d + 0], wgt * dx);
            atomicAdd(&out[H_OUT_ELEMS + 3 * d + 1], wgt * dy);
            atomicAdd(&out[H_OUT_ELEMS + 3 * d + 2], wgt * dz);
        }
    }
}

extern "C" void kernel_launch(void* const* d_in, const int* in_sizes, int n_in,
                              void* d_out, int out_size) {
    const float* h    = (const float*)d_in[0];
    const float* x    = (const float*)d_in[1];
    const void*  eidx = d_in[2];
    const float* dist = (const float*)d_in[3];
    const float* We1  = (const float*)d_in[4];
    const float* be1  = (const float*)d_in[5];
    const float* We2  = (const float*)d_in[6];
    const float* be2  = (const float*)d_in[7];
    const float* Wn1  = (const float*)d_in[8];
    const float* bn1  = (const float*)d_in[9];
    const float* Wn2  = (const float*)d_in[10];
    const float* bn2  = (const float*)d_in[11];
    const float* Wc1  = (const float*)d_in[12];
    const float* bc1  = (const float*)d_in[13];
    const float* Wc2  = (const float*)d_in[14];
    float* out = (float*)d_out;

    detect_idx_kernel<<<1, 32>>>((const int*)eidx);

    int total_w = 2 * NCOLS1 * NODE_DIM + NODE_DIM * HIDDEN;
    prep_weights_kernel<<<(total_w + 255) / 256, 256>>>(Wn1, Wc1, Wn2);
    prep_wf_kernel<<<2, 256>>>(Wn1, Wc1, We2, be2, bn1, bc1);

    int total_h = H_OUT_ELEMS + X_OUT_ELEMS;
    prep_h_kernel<<<(total_h + 255) / 256, 256>>>(h, x, out);

    cudaFuncSetAttribute(prep_P_kernel,
                         cudaFuncAttributeMaxDynamicSharedMemorySize, PP_SMEM_BYTES);
    prep_P_kernel<<<N_NODES / 64, THREADS, PP_SMEM_BYTES>>>();

    cudaFuncSetAttribute(egnn_edge_kernel,
                         cudaFuncAttributeMaxDynamicSharedMemorySize, MAIN_SMEM_BYTES);
    egnn_edge_kernel<<<N_EDGES / TILE_E, THREADS, MAIN_SMEM_BYTES>>>(
        eidx, dist, x, We1, be1, bn2, Wc2, out);
}